// round 16
// baseline (speedup 1.0000x reference)
#include <cuda_runtime.h>
#include <cuda_fp16.h>
#include <math.h>

#define NN 50000
#define EE 1600000
#define ETOT (EE + NN)          // edges + self loops
#define NBLK 196                // ceil(NN/256)

// ---------------- bit casts / conversions ----------------
__device__ __forceinline__ unsigned h2_to_u32(__half2 h) {
    return *reinterpret_cast<unsigned*>(&h);
}
__device__ __forceinline__ float2 u32_to_f2(unsigned u) {
    __half2 h = *reinterpret_cast<__half2*>(&u);
    return __half22float2(h);
}
__device__ __forceinline__ unsigned f2tf32(float f) {
    unsigned r;
    asm("cvt.rna.tf32.f32 %0, %1;" : "=r"(r) : "f"(f));
    return r;
}

// ---------------- scratch ----------------
__device__ __half    g_h1h[(size_t)NN * 128];   // layer1 linear out (fp16)
__device__ float     g_x2[(size_t)NN * 128];    // layer1 GAT out (relu)
__device__ __half    g_h2h[(size_t)NN * 64];    // layer2 linear out (fp16)
__device__ float     g_as1[NN * 2];
__device__ float     g_ad1[NN * 2];
__device__ float     g_as2[NN];
__device__ float     g_ad2[NN];
__device__ int       g_deg[NN];
__device__ int       g_rowptr[NN + 1];
__device__ int       g_cursor[NN];
__device__ int       g_csrc[ETOT];
__device__ int       g_bsum[256];
__device__ int       g_is64;
__device__ unsigned  g_wf1[256 * 128];          // W1 fragment-packed tf32
__device__ unsigned  g_wf2[128 * 64];           // W2 fragment-packed tf32

// ---------------- probe: edge dtype (g_deg zeroed by memsetAsync) ----------------
__global__ void k_probe(const int* __restrict__ ei32) {
    if (threadIdx.x == 0) {
        int all0 = 1;
        #pragma unroll
        for (int j = 0; j < 32; j++)
            if (ei32[2 * j + 1] != 0) all0 = 0;
        g_is64 = all0;           // int64 values < 50000 => odd words zero
        g_rowptr[NN] = ETOT;
    }
}

__device__ __forceinline__ int edge_at(const void* ei, long long idx) {
    if (g_is64) return (int)((const long long*)ei)[idx];
    return ((const int*)ei)[idx];
}

// ---------------- CSR build ----------------
__global__ void k_count(const void* __restrict__ ei) {
    int idx = blockIdx.x * 256 + threadIdx.x;
    if (idx >= ETOT) return;
    int d = (idx < EE) ? edge_at(ei, (long long)EE + idx) : (idx - EE);
    atomicAdd(&g_deg[d], 1);
}

__global__ void k_scanB() {   // chunk sums + exclusive scan of chunk sums
    __shared__ __align__(16) int sm[256];
    int t = threadIdx.x;
    int sum = 0;
    if (t < NBLK) {
        int base = t * 256;
        if (base + 256 <= NN) {
            const int4* p = (const int4*)&g_deg[base];
            #pragma unroll 8
            for (int j = 0; j < 64; j++) {
                int4 v = p[j];
                sum += v.x + v.y + v.z + v.w;
            }
        } else {
            for (int j = base; j < NN; j++) sum += g_deg[j];
        }
    }
    sm[t] = sum; __syncthreads();
    for (int off = 1; off < 256; off <<= 1) {
        int x = (t >= off) ? sm[t - off] : 0;
        __syncthreads();
        sm[t] += x;
        __syncthreads();
    }
    if (t < NBLK) g_bsum[t] = sm[t] - sum;   // exclusive
}

__global__ void k_scanC() {
    __shared__ __align__(16) int sm[256];
    int b = blockIdx.x, t = threadIdx.x;
    int i = b * 256 + t;
    int v = (i < NN) ? g_deg[i] : 0;
    sm[t] = v; __syncthreads();
    for (int off = 1; off < 256; off <<= 1) {
        int x = (t >= off) ? sm[t - off] : 0;
        __syncthreads();
        sm[t] += x;
        __syncthreads();
    }
    if (i < NN) {
        int rp = g_bsum[b] + sm[t] - v;
        g_rowptr[i] = rp;
        g_cursor[i] = rp;
    }
}

__global__ void k_scatter(const void* __restrict__ ei) {
    int idx = blockIdx.x * 256 + threadIdx.x;
    if (idx >= ETOT) return;
    int s, d;
    if (idx < EE) {
        s = edge_at(ei, idx);
        d = edge_at(ei, (long long)EE + idx);
    } else {
        s = d = idx - EE;
    }
    int pos = atomicAdd(&g_cursor[d], 1);
    g_csrc[pos] = s;
}

// ---------------- W fragment pre-pack ----------------
// B-frag mapping (m16n8k8.row.col, verified): for W[k][n]:
//   k8 = k>>3, nt = n>>3, lane = (n&7)*4 + (k&3), reg = (k>>2)&1
template<int K, int NOUT>
__global__ void k_packW(const float* __restrict__ W, unsigned* __restrict__ wf) {
    int i = blockIdx.x * 256 + threadIdx.x;
    if (i >= K * NOUT) return;
    int k = i / NOUT, n = i % NOUT;
    constexpr int NT = NOUT / 8;
    int k8 = k >> 3, nt = n >> 3;
    int lane = (n & 7) * 4 + (k & 3);
    int reg = (k >> 2) & 1;
    wf[(((k8 * NT + nt) * 32) + lane) * 2 + reg] = f2tf32(W[i]);
}

// ---------------- TF32 tensor-core GEMM + fused attention-score epilogue --------
// MT=64 rows, warps split 4(M) x 2(N-halves). A via register prefetch -> smem;
// B fragments from pre-packed global. launch_bounds(256,4) for 4 CTAs/SM.
template<int K, int NOUT, int H>
__global__ void __launch_bounds__(256, 4) k_gemm_tc(
        const float* __restrict__ X, const unsigned* __restrict__ wf,
        const float* __restrict__ att_s, const float* __restrict__ att_d,
        __half* __restrict__ Hout16, float* __restrict__ as_, float* __restrict__ ad_,
        int n) {
    constexpr int NT  = NOUT / 8;
    constexpr int NT2 = NT / 2;     // n-tiles per warp
    constexpr int MT  = 64;         // rows per block
    constexpr int KT  = 32;         // k chunk (4 k8-steps)
    constexpr int XS  = KT + 4;
    constexpr int NC  = K / KT;

    __shared__ __align__(16) unsigned xs[MT][XS];

    int tid = threadIdx.x;
    int w = tid >> 5, l = tid & 31;
    int tg = l & 3, gp = l >> 2;
    int wm = w & 3, wn = w >> 2;   // M group, N half
    int m0 = blockIdx.x * MT;
    int rowA = wm * 16 + gp;

    float acc[NT2][4];
#pragma unroll
    for (int nt = 0; nt < NT2; nt++)
#pragma unroll
        for (int c = 0; c < 4; c++) acc[nt][c] = 0.f;

    // staging coords recomputed inline (register relief): i = tid + j*256
    // r = i>>3 (row in tile), c4 = i&7 (float4 within row)
    float4 pre[2];
#pragma unroll
    for (int j = 0; j < 2; j++) {
        int i = tid + j * 256;
        int gr = m0 + (i >> 3);
        pre[j] = make_float4(0.f, 0.f, 0.f, 0.f);
        if (gr < n) pre[j] = *(const float4*)&X[(size_t)gr * K + (i & 7) * 4];
    }

#pragma unroll
    for (int kc = 0; kc < NC; kc++) {
#pragma unroll
        for (int j = 0; j < 2; j++) {
            int i = tid + j * 256;
            uint4 u;
            u.x = f2tf32(pre[j].x); u.y = f2tf32(pre[j].y);
            u.z = f2tf32(pre[j].z); u.w = f2tf32(pre[j].w);
            *(uint4*)&xs[i >> 3][(i & 7) * 4] = u;
        }
        __syncthreads();
        if (kc + 1 < NC) {
            int k0n = (kc + 1) * KT;
#pragma unroll
            for (int j = 0; j < 2; j++) {
                int i = tid + j * 256;
                int gr = m0 + (i >> 3);
                pre[j] = make_float4(0.f, 0.f, 0.f, 0.f);
                if (gr < n) pre[j] = *(const float4*)&X[(size_t)gr * K + k0n + (i & 7) * 4];
            }
        }
        int kb = kc * 4;
#pragma unroll
        for (int k8 = 0; k8 < 4; k8++) {
            unsigned a0 = xs[rowA][k8 * 8 + tg];
            unsigned a1 = xs[rowA + 8][k8 * 8 + tg];
            unsigned a2 = xs[rowA][k8 * 8 + tg + 4];
            unsigned a3 = xs[rowA + 8][k8 * 8 + tg + 4];
            const uint2* wp = (const uint2*)wf
                            + (size_t)(kb + k8) * NT * 32 + wn * NT2 * 32 + l;
#pragma unroll
            for (int nt = 0; nt < NT2; nt++) {
                uint2 B = wp[nt * 32];
                asm volatile(
                    "mma.sync.aligned.m16n8k8.row.col.f32.tf32.tf32.f32 "
                    "{%0,%1,%2,%3},{%4,%5,%6,%7},{%8,%9},{%0,%1,%2,%3};"
                    : "+f"(acc[nt][0]), "+f"(acc[nt][1]),
                      "+f"(acc[nt][2]), "+f"(acc[nt][3])
                    : "r"(a0), "r"(a1), "r"(a2), "r"(a3),
                      "r"(B.x), "r"(B.y));
            }
        }
        __syncthreads();
    }

    // ---- epilogue ----
    int r0 = m0 + rowA;
    int r1 = r0 + 8;

    float ps0 = 0.f, pd0 = 0.f, ps1 = 0.f, pd1 = 0.f;
#pragma unroll
    for (int nt = 0; nt < NT2; nt++) {
        int col = (wn * NT2 + nt) * 8 + tg * 2;
        float s0 = att_s[col], s1 = att_s[col + 1];
        float d0 = att_d[col], d1 = att_d[col + 1];
        ps0 += acc[nt][0] * s0 + acc[nt][1] * s1;
        pd0 += acc[nt][0] * d0 + acc[nt][1] * d1;
        ps1 += acc[nt][2] * s0 + acc[nt][3] * s1;
        pd1 += acc[nt][2] * d0 + acc[nt][3] * d1;
    }
#pragma unroll
    for (int o = 1; o < 4; o <<= 1) {
        ps0 += __shfl_xor_sync(0xffffffffu, ps0, o);
        pd0 += __shfl_xor_sync(0xffffffffu, pd0, o);
        ps1 += __shfl_xor_sync(0xffffffffu, ps1, o);
        pd1 += __shfl_xor_sync(0xffffffffu, pd1, o);
    }

    if (r0 < n) {
#pragma unroll
        for (int nt = 0; nt < NT2; nt++) {
            int col = (wn * NT2 + nt) * 8 + tg * 2;
            *(unsigned*)&Hout16[(size_t)r0 * NOUT + col] =
                h2_to_u32(__floats2half2_rn(acc[nt][0], acc[nt][1]));
        }
    }
    if (r1 < n) {
#pragma unroll
        for (int nt = 0; nt < NT2; nt++) {
            int col = (wn * NT2 + nt) * 8 + tg * 2;
            *(unsigned*)&Hout16[(size_t)r1 * NOUT + col] =
                h2_to_u32(__floats2half2_rn(acc[nt][2], acc[nt][3]));
        }
    }

    if (H == 2) {
        if (tg == 0) {
            if (r0 < n) { as_[r0 * 2 + wn] = ps0; ad_[r0 * 2 + wn] = pd0; }
            if (r1 < n) { as_[r1 * 2 + wn] = ps1; ad_[r1 * 2 + wn] = pd1; }
        }
    } else {
        float* sb = (float*)xs;
        if (wn == 1 && tg == 0) {
            sb[wm * 32 + gp * 2 + 0]       = ps0;
            sb[wm * 32 + gp * 2 + 1]       = pd0;
            sb[wm * 32 + (gp + 8) * 2 + 0] = ps1;
            sb[wm * 32 + (gp + 8) * 2 + 1] = pd1;
        }
        __syncthreads();
        if (wn == 0 && tg == 0) {
            ps0 += sb[wm * 32 + gp * 2 + 0];
            pd0 += sb[wm * 32 + gp * 2 + 1];
            ps1 += sb[wm * 32 + (gp + 8) * 2 + 0];
            pd1 += sb[wm * 32 + (gp + 8) * 2 + 1];
            if (r0 < n) { as_[r0] = ps0; ad_[r0] = pd0; }
            if (r1 < n) { as_[r1] = ps1; ad_[r1] = pd1; }
        }
    }
}

// ---------------- single-pass softmax aggregation (warp per dst node) ----------
// R10 batched form (unroll 4) — proven best agg structure.
template<int NOUT, int H, int VEC, bool RELU, bool LOGSM>
__global__ void k_agg(const __half* __restrict__ Hsrc,
                      const float* __restrict__ as_, const float* __restrict__ ad_,
                      const float* __restrict__ bias, float* __restrict__ out, int n) {
    int node = blockIdx.x * (blockDim.x / 32) + (threadIdx.x >> 5);
    int lane = threadIdx.x & 31;
    if (node >= n) return;

    int head = (lane * VEC) / 64;
    float adv0 = ad_[node * H];
    float adv1 = (H == 2) ? ad_[node * H + 1] : adv0;
    int beg = g_rowptr[node];
    int end = g_rowptr[node + 1];

    constexpr int EBK = (H == 2) ? 16 : 32;   // edges per batch

    float den = 0.f;
    float acc[VEC];
#pragma unroll
    for (int j = 0; j < VEC; j++) acc[j] = 0.f;

    const __half* Hbase = Hsrc + lane * VEC;

    for (int base = beg; base < end; base += EBK) {
        int myE = (H == 2) ? (base + (lane >> 1)) : (base + lane);
        int myH = (H == 2) ? (lane & 1) : 0;
        int sj = 0; float wv = 0.f;
        if (myE < end) {
            sj = g_csrc[myE];
            float v = as_[sj * H + myH] + (myH ? adv1 : adv0);
            v = v > 0.f ? v : 0.2f * v;
            wv = __expf(v);
        }
        int cnt = min(EBK, end - base);
        int e = 0;
        for (; e + 4 <= cnt; e += 4) {
            int s0, s1, s2, s3;
            float w0, w1, w2, w3;
            if (H == 2) {
                s0 = __shfl_sync(0xffffffffu, sj, 2 * (e + 0));
                s1 = __shfl_sync(0xffffffffu, sj, 2 * (e + 1));
                s2 = __shfl_sync(0xffffffffu, sj, 2 * (e + 2));
                s3 = __shfl_sync(0xffffffffu, sj, 2 * (e + 3));
                w0 = __shfl_sync(0xffffffffu, wv, 2 * (e + 0) + head);
                w1 = __shfl_sync(0xffffffffu, wv, 2 * (e + 1) + head);
                w2 = __shfl_sync(0xffffffffu, wv, 2 * (e + 2) + head);
                w3 = __shfl_sync(0xffffffffu, wv, 2 * (e + 3) + head);
            } else {
                s0 = __shfl_sync(0xffffffffu, sj, e + 0);
                s1 = __shfl_sync(0xffffffffu, sj, e + 1);
                s2 = __shfl_sync(0xffffffffu, sj, e + 2);
                s3 = __shfl_sync(0xffffffffu, sj, e + 3);
                w0 = __shfl_sync(0xffffffffu, wv, e + 0);
                w1 = __shfl_sync(0xffffffffu, wv, e + 1);
                w2 = __shfl_sync(0xffffffffu, wv, e + 2);
                w3 = __shfl_sync(0xffffffffu, wv, e + 3);
            }
            den += (w0 + w1) + (w2 + w3);
            if (VEC == 4) {
                uint2 u0 = *(const uint2*)(Hbase + (size_t)s0 * NOUT);
                uint2 u1 = *(const uint2*)(Hbase + (size_t)s1 * NOUT);
                uint2 u2 = *(const uint2*)(Hbase + (size_t)s2 * NOUT);
                uint2 u3 = *(const uint2*)(Hbase + (size_t)s3 * NOUT);
                float2 a0 = u32_to_f2(u0.x), a1 = u32_to_f2(u0.y);
                float2 b0 = u32_to_f2(u1.x), b1 = u32_to_f2(u1.y);
                float2 c0 = u32_to_f2(u2.x), c1 = u32_to_f2(u2.y);
                float2 d0 = u32_to_f2(u3.x), d1 = u32_to_f2(u3.y);
                acc[0] += (w0 * a0.x + w1 * b0.x) + (w2 * c0.x + w3 * d0.x);
                acc[1] += (w0 * a0.y + w1 * b0.y) + (w2 * c0.y + w3 * d0.y);
                acc[2] += (w0 * a1.x + w1 * b1.x) + (w2 * c1.x + w3 * d1.x);
                acc[3] += (w0 * a1.y + w1 * b1.y) + (w2 * c1.y + w3 * d1.y);
            } else {
                unsigned u0 = *(const unsigned*)(Hbase + (size_t)s0 * NOUT);
                unsigned u1 = *(const unsigned*)(Hbase + (size_t)s1 * NOUT);
                unsigned u2 = *(const unsigned*)(Hbase + (size_t)s2 * NOUT);
                unsigned u3 = *(const unsigned*)(Hbase + (size_t)s3 * NOUT);
                float2 a = u32_to_f2(u0), b = u32_to_f2(u1);
                float2 c = u32_to_f2(u2), d = u32_to_f2(u3);
                acc[0] += (w0 * a.x + w1 * b.x) + (w2 * c.x + w3 * d.x);
                acc[1] += (w0 * a.y + w1 * b.y) + (w2 * c.y + w3 * d.y);
            }
        }
        for (; e < cnt; e++) {
            int s  = __shfl_sync(0xffffffffu, sj, (H == 2) ? 2 * e : e);
            float ww = __shfl_sync(0xffffffffu, wv, (H == 2) ? 2 * e + head : e);
            den += ww;
            if (VEC == 4) {
                uint2 u = *(const uint2*)(Hbase + (size_t)s * NOUT);
                float2 a0 = u32_to_f2(u.x);
                float2 a1 = u32_to_f2(u.y);
                acc[0] += ww * a0.x; acc[1] += ww * a0.y;
                acc[2] += ww * a1.x; acc[3] += ww * a1.y;
            } else {
                unsigned u = *(const unsigned*)(Hbase + (size_t)s * NOUT);
                float2 a = u32_to_f2(u);
                acc[0] += ww * a.x; acc[1] += ww * a.y;
            }
        }
    }

    float inv = 1.f / (den + 1e-16f);
    float o[VEC];
#pragma unroll
    for (int j = 0; j < VEC; j++) {
        o[j] = acc[j] * inv + bias[lane * VEC + j];
        if (RELU) o[j] = fmaxf(o[j], 0.f);
    }

    if (LOGSM) {   // VEC==2, NOUT==64: warp holds all 64 outputs
        float m = fmaxf(o[0], o[1]);
#pragma unroll
        for (int off = 16; off > 0; off >>= 1)
            m = fmaxf(m, __shfl_xor_sync(0xffffffffu, m, off));
        float s_ = __expf(o[0] - m) + __expf(o[1] - m);
#pragma unroll
        for (int off = 16; off > 0; off >>= 1)
            s_ += __shfl_xor_sync(0xffffffffu, s_, off);
        float ls = m + logf(s_);
#pragma unroll
        for (int j = 0; j < VEC; j++) o[j] -= ls;
    }

    float* op = out + (size_t)node * NOUT + lane * VEC;
    if (VEC == 4) *(float4*)op = make_float4(o[0], o[1], o[2], o[3]);
    else          *(float2*)op = make_float2(o[0], o[1]);
}

// ---------------- launch ----------------
extern "C" void kernel_launch(void* const* d_in, const int* in_sizes, int n_in,
                              void* d_out, int out_size) {
    const float* x    = (const float*)d_in[0];
    const void*  ei   = d_in[1];
    const float* W1   = (const float*)d_in[2];
    const float* asw1 = (const float*)d_in[3];
    const float* adw1 = (const float*)d_in[4];
    const float* b1   = (const float*)d_in[5];
    const float* W2   = (const float*)d_in[6];
    const float* asw2 = (const float*)d_in[7];
    const float* adw2 = (const float*)d_in[8];
    const float* b2   = (const float*)d_in[9];
    float*       out  = (float*)d_out;

    const int EB = (ETOT + 255) / 256;
    const int WB = (NN + 7) / 8;
    const int GB = (NN + 63) / 64;      // gemm grid (64 rows/block)

    __half*   h1h = nullptr; cudaGetSymbolAddress((void**)&h1h, g_h1h);
    __half*   h2h = nullptr; cudaGetSymbolAddress((void**)&h2h, g_h2h);
    float*    x2  = nullptr; cudaGetSymbolAddress((void**)&x2,  g_x2);
    float*    as1 = nullptr; cudaGetSymbolAddress((void**)&as1, g_as1);
    float*    ad1 = nullptr; cudaGetSymbolAddress((void**)&ad1, g_ad1);
    float*    as2 = nullptr; cudaGetSymbolAddress((void**)&as2, g_as2);
    float*    ad2 = nullptr; cudaGetSymbolAddress((void**)&ad2, g_ad2);
    unsigned* wf1 = nullptr; cudaGetSymbolAddress((void**)&wf1, g_wf1);
    unsigned* wf2 = nullptr; cudaGetSymbolAddress((void**)&wf2, g_wf2);
    int*      deg = nullptr; cudaGetSymbolAddress((void**)&deg, g_deg);

    // side stream + events for fork/join (created on first, non-captured call)
    static cudaStream_t s2 = nullptr;
    static cudaEvent_t  e0 = nullptr, e1 = nullptr;
    if (!s2) {
        cudaStreamCreateWithFlags(&s2, cudaStreamNonBlocking);
        cudaEventCreateWithFlags(&e0, cudaEventDisableTiming);
        cudaEventCreateWithFlags(&e1, cudaEventDisableTiming);
    }

    // fork: GEMM chain on s2, CSR chain on the main stream
    cudaEventRecord(e0, 0);
    cudaStreamWaitEvent(s2, e0, 0);

    cudaMemsetAsync(deg, 0, NN * sizeof(int), 0);                            // main
    k_probe<<<1, 32>>>((const int*)ei);                                      // main
    k_count<<<EB, 256>>>(ei);                                                // main
    k_packW<256, 128><<<(256 * 128 + 255) / 256, 256, 0, s2>>>(W1, wf1);     // s2
    k_gemm_tc<256, 128, 2><<<GB, 256, 0, s2>>>(                              // s2
        x, wf1, asw1, adw1, h1h, as1, ad1, NN);
    k_packW<128, 64><<<(128 * 64 + 255) / 256, 256, 0, s2>>>(W2, wf2);       // s2
    cudaEventRecord(e1, s2);

    k_scanB<<<1, 256>>>();                                                   // main
    k_scanC<<<NBLK, 256>>>();                                                // main
    k_scatter<<<EB, 256>>>(ei);                                              // main

    // join: aggregation needs CSR (main) + h1/scores/wf2 (s2)
    cudaStreamWaitEvent(0, e1, 0);

    k_agg<128, 2, 4, true, false><<<WB, 256>>>(h1h, as1, ad1, b1, x2, NN);
    k_gemm_tc<128, 64, 1><<<GB, 256>>>(
        x2, wf2, asw2, adw2, h2h, as2, ad2, NN);
    k_agg<64, 1, 2, false, true><<<WB, 256>>>(h2h, as2, ad2, b2, out, NN);
}

// round 17
// speedup vs baseline: 1.0984x; 1.0984x over previous
#include <cuda_runtime.h>
#include <cuda_fp16.h>
#include <math.h>

#define NN 50000
#define EE 1600000
#define ETOT (EE + NN)          // edges + self loops
#define NBLK 196                // ceil(NN/256)

// ---------------- bit casts / conversions ----------------
__device__ __forceinline__ unsigned h2_to_u32(__half2 h) {
    return *reinterpret_cast<unsigned*>(&h);
}
__device__ __forceinline__ float2 u32_to_f2(unsigned u) {
    __half2 h = *reinterpret_cast<__half2*>(&u);
    return __half22float2(h);
}
__device__ __forceinline__ unsigned f2tf32(float f) {
    unsigned r;
    asm("cvt.rna.tf32.f32 %0, %1;" : "=r"(r) : "f"(f));
    return r;
}

// ---------------- scratch ----------------
__device__ __half    g_h1h[(size_t)NN * 128];   // layer1 linear out (fp16)
__device__ float     g_x2[(size_t)NN * 128];    // layer1 GAT out (relu)
__device__ __half    g_h2h[(size_t)NN * 64];    // layer2 linear out (fp16)
__device__ float     g_as1[NN * 2];
__device__ float     g_ad1[NN * 2];
__device__ float     g_as2[NN];
__device__ float     g_ad2[NN];
__device__ int       g_deg[NN];
__device__ int       g_rowptr[NN + 1];
__device__ int       g_cursor[NN];
__device__ int       g_csrc[ETOT];
__device__ int       g_bsum[256];
__device__ int       g_is64;
__device__ unsigned  g_wf1[256 * 128];          // W1 fragment-packed tf32
__device__ unsigned  g_wf2[128 * 64];           // W2 fragment-packed tf32

// ---------------- probe: edge dtype (g_deg zeroed by memsetAsync) ----------------
__global__ void k_probe(const int* __restrict__ ei32) {
    if (threadIdx.x == 0) {
        int all0 = 1;
        #pragma unroll
        for (int j = 0; j < 32; j++)
            if (ei32[2 * j + 1] != 0) all0 = 0;
        g_is64 = all0;           // int64 values < 50000 => odd words zero
        g_rowptr[NN] = ETOT;
    }
}

__device__ __forceinline__ int edge_at(const void* ei, long long idx) {
    if (g_is64) return (int)((const long long*)ei)[idx];
    return ((const int*)ei)[idx];
}

// ---------------- CSR build ----------------
__global__ void k_count(const void* __restrict__ ei) {
    int idx = blockIdx.x * 256 + threadIdx.x;
    if (idx >= ETOT) return;
    int d = (idx < EE) ? edge_at(ei, (long long)EE + idx) : (idx - EE);
    atomicAdd(&g_deg[d], 1);
}

__global__ void k_scanB() {   // chunk sums + exclusive scan of chunk sums
    __shared__ __align__(16) int sm[256];
    int t = threadIdx.x;
    int sum = 0;
    if (t < NBLK) {
        int base = t * 256;
        if (base + 256 <= NN) {
            const int4* p = (const int4*)&g_deg[base];
            #pragma unroll 8
            for (int j = 0; j < 64; j++) {
                int4 v = p[j];
                sum += v.x + v.y + v.z + v.w;
            }
        } else {
            for (int j = base; j < NN; j++) sum += g_deg[j];
        }
    }
    sm[t] = sum; __syncthreads();
    for (int off = 1; off < 256; off <<= 1) {
        int x = (t >= off) ? sm[t - off] : 0;
        __syncthreads();
        sm[t] += x;
        __syncthreads();
    }
    if (t < NBLK) g_bsum[t] = sm[t] - sum;   // exclusive
}

__global__ void k_scanC() {
    __shared__ __align__(16) int sm[256];
    int b = blockIdx.x, t = threadIdx.x;
    int i = b * 256 + t;
    int v = (i < NN) ? g_deg[i] : 0;
    sm[t] = v; __syncthreads();
    for (int off = 1; off < 256; off <<= 1) {
        int x = (t >= off) ? sm[t - off] : 0;
        __syncthreads();
        sm[t] += x;
        __syncthreads();
    }
    if (i < NN) {
        int rp = g_bsum[b] + sm[t] - v;
        g_rowptr[i] = rp;
        g_cursor[i] = rp;
    }
}

__global__ void k_scatter(const void* __restrict__ ei) {
    int idx = blockIdx.x * 256 + threadIdx.x;
    if (idx >= ETOT) return;
    int s, d;
    if (idx < EE) {
        s = edge_at(ei, idx);
        d = edge_at(ei, (long long)EE + idx);
    } else {
        s = d = idx - EE;
    }
    int pos = atomicAdd(&g_cursor[d], 1);
    g_csrc[pos] = s;
}

// ---------------- W fragment pre-pack ----------------
// B-frag mapping (m16n8k8.row.col, verified): for W[k][n]:
//   k8 = k>>3, nt = n>>3, lane = (n&7)*4 + (k&3), reg = (k>>2)&1
template<int K, int NOUT>
__global__ void k_packW(const float* __restrict__ W, unsigned* __restrict__ wf) {
    int i = blockIdx.x * 256 + threadIdx.x;
    if (i >= K * NOUT) return;
    int k = i / NOUT, n = i % NOUT;
    constexpr int NT = NOUT / 8;
    int k8 = k >> 3, nt = n >> 3;
    int lane = (n & 7) * 4 + (k & 3);
    int reg = (k >> 2) & 1;
    wf[(((k8 * NT + nt) * 32) + lane) * 2 + reg] = f2tf32(W[i]);
}

// ---------------- TF32 tensor-core GEMM + fused attention-score epilogue --------
// MT=64 rows, warps split 4(M) x 2(N-halves). A via register prefetch -> smem;
// B fragments from pre-packed global. R10-proven config: launch_bounds(256,3).
template<int K, int NOUT, int H>
__global__ void __launch_bounds__(256, 3) k_gemm_tc(
        const float* __restrict__ X, const unsigned* __restrict__ wf,
        const float* __restrict__ att_s, const float* __restrict__ att_d,
        __half* __restrict__ Hout16, float* __restrict__ as_, float* __restrict__ ad_,
        int n) {
    constexpr int NT  = NOUT / 8;
    constexpr int NT2 = NT / 2;     // n-tiles per warp
    constexpr int MT  = 64;         // rows per block
    constexpr int KT  = 32;         // k chunk (4 k8-steps)
    constexpr int XS  = KT + 4;
    constexpr int NC  = K / KT;

    __shared__ __align__(16) unsigned xs[MT][XS];

    int tid = threadIdx.x;
    int w = tid >> 5, l = tid & 31;
    int tg = l & 3, gp = l >> 2;
    int wm = w & 3, wn = w >> 2;   // M group, N half
    int m0 = blockIdx.x * MT;
    int rowA = wm * 16 + gp;

    float acc[NT2][4];
#pragma unroll
    for (int nt = 0; nt < NT2; nt++)
#pragma unroll
        for (int c = 0; c < 4; c++) acc[nt][c] = 0.f;

    // staging coords: 64*8=512 float4, 2 per thread
    int sr[2], sc4[2];
#pragma unroll
    for (int j = 0; j < 2; j++) {
        int i = tid + j * 256;
        sr[j] = i >> 3;
        sc4[j] = i & 7;
    }
    float4 pre[2];
#pragma unroll
    for (int j = 0; j < 2; j++) {
        int gr = m0 + sr[j];
        pre[j] = make_float4(0.f, 0.f, 0.f, 0.f);
        if (gr < n) pre[j] = *(const float4*)&X[(size_t)gr * K + sc4[j] * 4];
    }

#pragma unroll
    for (int kc = 0; kc < NC; kc++) {
#pragma unroll
        for (int j = 0; j < 2; j++) {
            uint4 u;
            u.x = f2tf32(pre[j].x); u.y = f2tf32(pre[j].y);
            u.z = f2tf32(pre[j].z); u.w = f2tf32(pre[j].w);
            *(uint4*)&xs[sr[j]][sc4[j] * 4] = u;
        }
        __syncthreads();
        if (kc + 1 < NC) {
            int k0n = (kc + 1) * KT;
#pragma unroll
            for (int j = 0; j < 2; j++) {
                int gr = m0 + sr[j];
                pre[j] = make_float4(0.f, 0.f, 0.f, 0.f);
                if (gr < n) pre[j] = *(const float4*)&X[(size_t)gr * K + k0n + sc4[j] * 4];
            }
        }
        int kb = kc * 4;
#pragma unroll
        for (int k8 = 0; k8 < 4; k8++) {
            unsigned a0 = xs[rowA][k8 * 8 + tg];
            unsigned a1 = xs[rowA + 8][k8 * 8 + tg];
            unsigned a2 = xs[rowA][k8 * 8 + tg + 4];
            unsigned a3 = xs[rowA + 8][k8 * 8 + tg + 4];
            const uint2* wp = (const uint2*)wf
                            + (size_t)(kb + k8) * NT * 32 + wn * NT2 * 32 + l;
#pragma unroll
            for (int nt = 0; nt < NT2; nt++) {
                uint2 B = wp[nt * 32];
                asm volatile(
                    "mma.sync.aligned.m16n8k8.row.col.f32.tf32.tf32.f32 "
                    "{%0,%1,%2,%3},{%4,%5,%6,%7},{%8,%9},{%0,%1,%2,%3};"
                    : "+f"(acc[nt][0]), "+f"(acc[nt][1]),
                      "+f"(acc[nt][2]), "+f"(acc[nt][3])
                    : "r"(a0), "r"(a1), "r"(a2), "r"(a3),
                      "r"(B.x), "r"(B.y));
            }
        }
        __syncthreads();
    }

    // ---- epilogue ----
    int r0 = m0 + rowA;
    int r1 = r0 + 8;

    float ps0 = 0.f, pd0 = 0.f, ps1 = 0.f, pd1 = 0.f;
#pragma unroll
    for (int nt = 0; nt < NT2; nt++) {
        int col = (wn * NT2 + nt) * 8 + tg * 2;
        float s0 = att_s[col], s1 = att_s[col + 1];
        float d0 = att_d[col], d1 = att_d[col + 1];
        ps0 += acc[nt][0] * s0 + acc[nt][1] * s1;
        pd0 += acc[nt][0] * d0 + acc[nt][1] * d1;
        ps1 += acc[nt][2] * s0 + acc[nt][3] * s1;
        pd1 += acc[nt][2] * d0 + acc[nt][3] * d1;
    }
#pragma unroll
    for (int o = 1; o < 4; o <<= 1) {
        ps0 += __shfl_xor_sync(0xffffffffu, ps0, o);
        pd0 += __shfl_xor_sync(0xffffffffu, pd0, o);
        ps1 += __shfl_xor_sync(0xffffffffu, ps1, o);
        pd1 += __shfl_xor_sync(0xffffffffu, pd1, o);
    }

    if (r0 < n) {
#pragma unroll
        for (int nt = 0; nt < NT2; nt++) {
            int col = (wn * NT2 + nt) * 8 + tg * 2;
            *(unsigned*)&Hout16[(size_t)r0 * NOUT + col] =
                h2_to_u32(__floats2half2_rn(acc[nt][0], acc[nt][1]));
        }
    }
    if (r1 < n) {
#pragma unroll
        for (int nt = 0; nt < NT2; nt++) {
            int col = (wn * NT2 + nt) * 8 + tg * 2;
            *(unsigned*)&Hout16[(size_t)r1 * NOUT + col] =
                h2_to_u32(__floats2half2_rn(acc[nt][2], acc[nt][3]));
        }
    }

    if (H == 2) {
        // each N-half is exactly one head
        if (tg == 0) {
            if (r0 < n) { as_[r0 * 2 + wn] = ps0; ad_[r0 * 2 + wn] = pd0; }
            if (r1 < n) { as_[r1 * 2 + wn] = ps1; ad_[r1 * 2 + wn] = pd1; }
        }
    } else {
        // combine the two N-half partials via smem (deterministic)
        float* sb = (float*)xs;   // mainloop done (post-sync), safe to reuse
        if (wn == 1 && tg == 0) {
            sb[wm * 32 + gp * 2 + 0]       = ps0;
            sb[wm * 32 + gp * 2 + 1]       = pd0;
            sb[wm * 32 + (gp + 8) * 2 + 0] = ps1;
            sb[wm * 32 + (gp + 8) * 2 + 1] = pd1;
        }
        __syncthreads();
        if (wn == 0 && tg == 0) {
            ps0 += sb[wm * 32 + gp * 2 + 0];
            pd0 += sb[wm * 32 + gp * 2 + 1];
            ps1 += sb[wm * 32 + (gp + 8) * 2 + 0];
            pd1 += sb[wm * 32 + (gp + 8) * 2 + 1];
            if (r0 < n) { as_[r0] = ps0; ad_[r0] = pd0; }
            if (r1 < n) { as_[r1] = ps1; ad_[r1] = pd1; }
        }
    }
}

// ---------------- single-pass softmax aggregation (warp per dst node) ----------
// R10 batched form (unroll 4) — proven best agg structure.
template<int NOUT, int H, int VEC, bool RELU, bool LOGSM>
__global__ void k_agg(const __half* __restrict__ Hsrc,
                      const float* __restrict__ as_, const float* __restrict__ ad_,
                      const float* __restrict__ bias, float* __restrict__ out, int n) {
    int node = blockIdx.x * (blockDim.x / 32) + (threadIdx.x >> 5);
    int lane = threadIdx.x & 31;
    if (node >= n) return;

    int head = (lane * VEC) / 64;
    float adv0 = ad_[node * H];
    float adv1 = (H == 2) ? ad_[node * H + 1] : adv0;
    int beg = g_rowptr[node];
    int end = g_rowptr[node + 1];

    constexpr int EBK = (H == 2) ? 16 : 32;   // edges per batch

    float den = 0.f;
    float acc[VEC];
#pragma unroll
    for (int j = 0; j < VEC; j++) acc[j] = 0.f;

    const __half* Hbase = Hsrc + lane * VEC;

    for (int base = beg; base < end; base += EBK) {
        int myE = (H == 2) ? (base + (lane >> 1)) : (base + lane);
        int myH = (H == 2) ? (lane & 1) : 0;
        int sj = 0; float wv = 0.f;
        if (myE < end) {
            sj = g_csrc[myE];
            float v = as_[sj * H + myH] + (myH ? adv1 : adv0);
            v = v > 0.f ? v : 0.2f * v;
            wv = __expf(v);
        }
        int cnt = min(EBK, end - base);
        int e = 0;
        for (; e + 4 <= cnt; e += 4) {
            int s0, s1, s2, s3;
            float w0, w1, w2, w3;
            if (H == 2) {
                s0 = __shfl_sync(0xffffffffu, sj, 2 * (e + 0));
                s1 = __shfl_sync(0xffffffffu, sj, 2 * (e + 1));
                s2 = __shfl_sync(0xffffffffu, sj, 2 * (e + 2));
                s3 = __shfl_sync(0xffffffffu, sj, 2 * (e + 3));
                w0 = __shfl_sync(0xffffffffu, wv, 2 * (e + 0) + head);
                w1 = __shfl_sync(0xffffffffu, wv, 2 * (e + 1) + head);
                w2 = __shfl_sync(0xffffffffu, wv, 2 * (e + 2) + head);
                w3 = __shfl_sync(0xffffffffu, wv, 2 * (e + 3) + head);
            } else {
                s0 = __shfl_sync(0xffffffffu, sj, e + 0);
                s1 = __shfl_sync(0xffffffffu, sj, e + 1);
                s2 = __shfl_sync(0xffffffffu, sj, e + 2);
                s3 = __shfl_sync(0xffffffffu, sj, e + 3);
                w0 = __shfl_sync(0xffffffffu, wv, e + 0);
                w1 = __shfl_sync(0xffffffffu, wv, e + 1);
                w2 = __shfl_sync(0xffffffffu, wv, e + 2);
                w3 = __shfl_sync(0xffffffffu, wv, e + 3);
            }
            den += (w0 + w1) + (w2 + w3);
            if (VEC == 4) {
                uint2 u0 = *(const uint2*)(Hbase + (size_t)s0 * NOUT);
                uint2 u1 = *(const uint2*)(Hbase + (size_t)s1 * NOUT);
                uint2 u2 = *(const uint2*)(Hbase + (size_t)s2 * NOUT);
                uint2 u3 = *(const uint2*)(Hbase + (size_t)s3 * NOUT);
                float2 a0 = u32_to_f2(u0.x), a1 = u32_to_f2(u0.y);
                float2 b0 = u32_to_f2(u1.x), b1 = u32_to_f2(u1.y);
                float2 c0 = u32_to_f2(u2.x), c1 = u32_to_f2(u2.y);
                float2 d0 = u32_to_f2(u3.x), d1 = u32_to_f2(u3.y);
                acc[0] += (w0 * a0.x + w1 * b0.x) + (w2 * c0.x + w3 * d0.x);
                acc[1] += (w0 * a0.y + w1 * b0.y) + (w2 * c0.y + w3 * d0.y);
                acc[2] += (w0 * a1.x + w1 * b1.x) + (w2 * c1.x + w3 * d1.x);
                acc[3] += (w0 * a1.y + w1 * b1.y) + (w2 * c1.y + w3 * d1.y);
            } else {
                unsigned u0 = *(const unsigned*)(Hbase + (size_t)s0 * NOUT);
                unsigned u1 = *(const unsigned*)(Hbase + (size_t)s1 * NOUT);
                unsigned u2 = *(const unsigned*)(Hbase + (size_t)s2 * NOUT);
                unsigned u3 = *(const unsigned*)(Hbase + (size_t)s3 * NOUT);
                float2 a = u32_to_f2(u0), b = u32_to_f2(u1);
                float2 c = u32_to_f2(u2), d = u32_to_f2(u3);
                acc[0] += (w0 * a.x + w1 * b.x) + (w2 * c.x + w3 * d.x);
                acc[1] += (w0 * a.y + w1 * b.y) + (w2 * c.y + w3 * d.y);
            }
        }
        for (; e < cnt; e++) {
            int s  = __shfl_sync(0xffffffffu, sj, (H == 2) ? 2 * e : e);
            float ww = __shfl_sync(0xffffffffu, wv, (H == 2) ? 2 * e + head : e);
            den += ww;
            if (VEC == 4) {
                uint2 u = *(const uint2*)(Hbase + (size_t)s * NOUT);
                float2 a0 = u32_to_f2(u.x);
                float2 a1 = u32_to_f2(u.y);
                acc[0] += ww * a0.x; acc[1] += ww * a0.y;
                acc[2] += ww * a1.x; acc[3] += ww * a1.y;
            } else {
                unsigned u = *(const unsigned*)(Hbase + (size_t)s * NOUT);
                float2 a = u32_to_f2(u);
                acc[0] += ww * a.x; acc[1] += ww * a.y;
            }
        }
    }

    float inv = 1.f / (den + 1e-16f);
    float o[VEC];
#pragma unroll
    for (int j = 0; j < VEC; j++) {
        o[j] = acc[j] * inv + bias[lane * VEC + j];
        if (RELU) o[j] = fmaxf(o[j], 0.f);
    }

    if (LOGSM) {   // VEC==2, NOUT==64: warp holds all 64 outputs
        float m = fmaxf(o[0], o[1]);
#pragma unroll
        for (int off = 16; off > 0; off >>= 1)
            m = fmaxf(m, __shfl_xor_sync(0xffffffffu, m, off));
        float s_ = __expf(o[0] - m) + __expf(o[1] - m);
#pragma unroll
        for (int off = 16; off > 0; off >>= 1)
            s_ += __shfl_xor_sync(0xffffffffu, s_, off);
        float ls = m + logf(s_);
#pragma unroll
        for (int j = 0; j < VEC; j++) o[j] -= ls;
    }

    float* op = out + (size_t)node * NOUT + lane * VEC;
    if (VEC == 4) *(float4*)op = make_float4(o[0], o[1], o[2], o[3]);
    else          *(float2*)op = make_float2(o[0], o[1]);
}

// ---------------- launch ----------------
extern "C" void kernel_launch(void* const* d_in, const int* in_sizes, int n_in,
                              void* d_out, int out_size) {
    const float* x    = (const float*)d_in[0];
    const void*  ei   = d_in[1];
    const float* W1   = (const float*)d_in[2];
    const float* asw1 = (const float*)d_in[3];
    const float* adw1 = (const float*)d_in[4];
    const float* b1   = (const float*)d_in[5];
    const float* W2   = (const float*)d_in[6];
    const float* asw2 = (const float*)d_in[7];
    const float* adw2 = (const float*)d_in[8];
    const float* b2   = (const float*)d_in[9];
    float*       out  = (float*)d_out;

    const int EB = (ETOT + 255) / 256;
    const int WB = (NN + 7) / 8;
    const int GB = (NN + 63) / 64;      // gemm grid (64 rows/block)

    __half*   h1h = nullptr; cudaGetSymbolAddress((void**)&h1h, g_h1h);
    __half*   h2h = nullptr; cudaGetSymbolAddress((void**)&h2h, g_h2h);
    float*    x2  = nullptr; cudaGetSymbolAddress((void**)&x2,  g_x2);
    float*    as1 = nullptr; cudaGetSymbolAddress((void**)&as1, g_as1);
    float*    ad1 = nullptr; cudaGetSymbolAddress((void**)&ad1, g_ad1);
    float*    as2 = nullptr; cudaGetSymbolAddress((void**)&as2, g_as2);
    float*    ad2 = nullptr; cudaGetSymbolAddress((void**)&ad2, g_ad2);
    unsigned* wf1 = nullptr; cudaGetSymbolAddress((void**)&wf1, g_wf1);
    unsigned* wf2 = nullptr; cudaGetSymbolAddress((void**)&wf2, g_wf2);
    int*      deg = nullptr; cudaGetSymbolAddress((void**)&deg, g_deg);

    // side stream + events for fork/join (created on first, non-captured call)
    static cudaStream_t s2 = nullptr;
    static cudaEvent_t  e0 = nullptr, e1 = nullptr;
    if (!s2) {
        cudaStreamCreateWithFlags(&s2, cudaStreamNonBlocking);
        cudaEventCreateWithFlags(&e0, cudaEventDisableTiming);
        cudaEventCreateWithFlags(&e1, cudaEventDisableTiming);
    }

    // fork: GEMM chain on s2, CSR chain on the main stream
    cudaEventRecord(e0, 0);
    cudaStreamWaitEvent(s2, e0, 0);

    cudaMemsetAsync(deg, 0, NN * sizeof(int), 0);                            // main
    k_probe<<<1, 32>>>((const int*)ei);                                      // main
    k_count<<<EB, 256>>>(ei);                                                // main
    k_packW<256, 128><<<(256 * 128 + 255) / 256, 256, 0, s2>>>(W1, wf1);     // s2
    k_gemm_tc<256, 128, 2><<<GB, 256, 0, s2>>>(                              // s2
        x, wf1, asw1, adw1, h1h, as1, ad1, NN);
    k_packW<128, 64><<<(128 * 64 + 255) / 256, 256, 0, s2>>>(W2, wf2);       // s2
    cudaEventRecord(e1, s2);

    k_scanB<<<1, 256>>>();                                                   // main
    k_scanC<<<NBLK, 256>>>();                                                // main
    k_scatter<<<EB, 256>>>(ei);                                              // main

    // join: aggregation needs CSR (main) + h1/scores/wf2 (s2)
    cudaStreamWaitEvent(0, e1, 0);

    k_agg<128, 2, 4, true, false><<<WB, 256>>>(h1h, as1, ad1, b1, x2, NN);
    k_gemm_tc<128, 64, 1><<<GB, 256>>>(
        x2, wf2, asw2, adw2, h2h, as2, ad2, NN);
    k_agg<64, 1, 2, false, true><<<WB, 256>>>(h2h, as2, ad2, b2, out, NN);
}